// round 2
// baseline (speedup 1.0000x reference)
#include <cuda_runtime.h>
#include <cstdint>
#include <cstddef>

// Problem dims (fixed): B=8192, I=H=O=4096. K2 = I+H = 8192 (fused GEMM1+2).
// out = [output (8192x4096) ; hidden_new (8192x4096)] float32, 67108864 elems.
//
// Exactness scheme:
//   pre_act is computed EXACTLY in fixed point (scale 2^-20) via 3 balanced
//   signed-int8 limbs (base 256) x ternary int8 weights on s8 tensor cores
//   (s32 accumulate, no overflow: |sum| <= 8192*128*1 * ... << 2^31).
//   Ternary threshold is an exact integer compare (|pre|*2^20 vs 524288).
//   Output GEMM is ternary x ternary -> exact int, exact fp32 convert.

// ---------------- scratch (static device globals; no allocation) ----------------
// __align__(256): these are vector-accessed (char4/int2/int4); alignment of a
// plain int8_t[] is otherwise not guaranteed by the language.
__device__ __align__(256) int8_t g_A [3ULL * 8192 * 8192];   // limb planes of [x|hidden], [M][K2]
__device__ __align__(256) int8_t g_W [(size_t)4096 * 8192];  // [Wi|Wh] ternary, [N][K2]
__device__ __align__(256) int8_t g_Wo[(size_t)4096 * 4096];  // Wo ternary, [N][K]
__device__ __align__(256) int8_t g_Hq[(size_t)8192 * 4096];  // hidden_new ternary, [M][K]
__device__ __align__(256) int    g_C [3ULL * 8192 * 4096];   // limb GEMM results, 3 planes

// ---------------- weight ternarization: q = clip(rint(w), -1, 1) ----------------
__global__ void k_quant(const float* __restrict__ Wi, const float* __restrict__ Wh,
                        const float* __restrict__ Wo) {
    size_t idx = (size_t)blockIdx.x * blockDim.x + threadIdx.x;   // one float4
    const size_t PER = (size_t)4096 * 4096 / 4;                   // 4194304
    if (idx >= 3 * PER) return;
    int w = (int)(idx / PER);
    size_t e = idx % PER;
    int row = (int)(e >> 10);
    int c4  = (int)(e & 1023);
    const float4 v = reinterpret_cast<const float4*>(w == 0 ? Wi : (w == 1 ? Wh : Wo))[e];
    float rx = fminf(1.f, fmaxf(-1.f, rintf(v.x)));
    float ry = fminf(1.f, fmaxf(-1.f, rintf(v.y)));
    float rz = fminf(1.f, fmaxf(-1.f, rintf(v.z)));
    float rw = fminf(1.f, fmaxf(-1.f, rintf(v.w)));
    char4 q = make_char4((int8_t)rx, (int8_t)ry, (int8_t)rz, (int8_t)rw);
    if (w == 0)      *reinterpret_cast<char4*>(&g_W [(size_t)row * 8192 + c4 * 4])        = q;
    else if (w == 1) *reinterpret_cast<char4*>(&g_W [(size_t)row * 8192 + 4096 + c4 * 4]) = q;
    else             *reinterpret_cast<char4*>(&g_Wo[(size_t)row * 4096 + c4 * 4])        = q;
}

// ------------- fixed-point + balanced base-256 limb decomposition of A -------------
// v = clamp(rint(x * 2^20), +-8355711);  v = d0 + 256*d1 + 65536*d2, d_j in [-128,127]
__global__ void k_limb(const float* __restrict__ x, const float* __restrict__ h) {
    size_t idx = (size_t)blockIdx.x * blockDim.x + threadIdx.x;   // one float4
    const size_t PER = (size_t)8192 * 4096 / 4;                   // 8388608
    if (idx >= 2 * PER) return;
    int s = (int)(idx / PER);          // 0 = x (cols 0..4095), 1 = hidden (cols 4096..8191)
    size_t e = idx % PER;
    int row = (int)(e >> 10);
    int c4  = (int)(e & 1023);
    float4 v = reinterpret_cast<const float4*>(s ? h : x)[e];
    float f[4] = {v.x, v.y, v.z, v.w};
    signed char d0[4], d1[4], d2[4];
#pragma unroll
    for (int j = 0; j < 4; ++j) {
        float r = rintf(f[j] * 1048576.0f);
        r = fminf(8355711.0f, fmaxf(-8355711.0f, r));
        int t = (int)r;
        int e0 = ((t + 128) & 255) - 128; t = (t - e0) >> 8;
        int e1 = ((t + 128) & 255) - 128; t = (t - e1) >> 8;
        d0[j] = (signed char)e0; d1[j] = (signed char)e1; d2[j] = (signed char)t;
    }
    const size_t PLANE = (size_t)8192 * 8192;
    size_t off = (size_t)row * 8192 + (size_t)s * 4096 + (size_t)c4 * 4;
    *reinterpret_cast<char4*>(&g_A[off])             = make_char4(d0[0], d0[1], d0[2], d0[3]);
    *reinterpret_cast<char4*>(&g_A[PLANE + off])     = make_char4(d1[0], d1[1], d1[2], d1[3]);
    *reinterpret_cast<char4*>(&g_A[2 * PLANE + off]) = make_char4(d2[0], d2[1], d2[2], d2[3]);
}

// -------- limb recombination (exact int64) + ternarize: writes hidden_new --------
__global__ void k_combine(float* __restrict__ outHid) {
    size_t idx = (size_t)blockIdx.x * blockDim.x + threadIdx.x;   // one int4 (4 elems)
    const size_t N4 = (size_t)8192 * 4096 / 4;                    // 8388608
    if (idx >= N4) return;
    const int4* C = reinterpret_cast<const int4*>(g_C);
    int4 a = C[idx], b = C[idx + N4], c = C[idx + 2 * N4];
    int av[4] = {a.x, a.y, a.z, a.w};
    int bv[4] = {b.x, b.y, b.z, b.w};
    int cv[4] = {c.x, c.y, c.z, c.w};
    float o[4]; signed char hq[4];
#pragma unroll
    for (int j = 0; j < 4; ++j) {
        long long S = (long long)av[j] + 256LL * bv[j] + 65536LL * cv[j];  // pre * 2^20, exact
        // round-half-even then clip: |pre| == 0.5 exactly -> 0; strict > -> +-1
        int hv = (S > 524288LL) ? 1 : ((S < -524288LL) ? -1 : 0);
        o[j] = (float)hv;
        hq[j] = (signed char)hv;
    }
    if (outHid) reinterpret_cast<float4*>(outHid)[idx] = make_float4(o[0], o[1], o[2], o[3]);
    *reinterpret_cast<char4*>(&g_Hq[idx * 4]) = make_char4(hq[0], hq[1], hq[2], hq[3]);
}

// ---------------- int8 tensor-core GEMM: C[M,N] = A[M,K] * B[N,K]^T ----------------
// 128x128 CTA tile, BK=64, 8 warps (2x4), 64x32 warp tile, cp.async double-buffer.
// 80B-padded smem rows: ldmatrix row addresses hit start-banks
// {0,20,8,28,16,4,24,12} -> fully conflict-free.
#define CP16(smaddr, gptr) \
    asm volatile("cp.async.cg.shared.global [%0], [%1], 16;" :: "r"(smaddr), "l"(gptr))

template <int KDIM, bool OUTF>
__global__ __launch_bounds__(256) void k_gemm(float* __restrict__ outF) {
    __shared__ int8_t sA[2][128 * 80];
    __shared__ int8_t sB[2][128 * 80];

    const int bm = blockIdx.y, bn = blockIdx.x, z = blockIdx.z;
    const size_t APLANE = (size_t)8192 * 8192;
    const size_t CPLANE = (size_t)8192 * 4096;

    const int8_t* A  = (OUTF ? g_Hq : g_A + (size_t)z * APLANE) + (size_t)bm * 128 * KDIM;
    const int8_t* Bp = (OUTF ? g_Wo : g_W) + (size_t)bn * 128 * KDIM;

    const int tid = threadIdx.x;
    const int lr  = tid >> 2;            // 0..63 (row; +64 for second half)
    const int lco = (tid & 3) * 16;      // 16B chunk within 64B k-slab

    unsigned aSm[2], bSm[2];
    aSm[0] = (unsigned)__cvta_generic_to_shared(&sA[0][0]);
    aSm[1] = (unsigned)__cvta_generic_to_shared(&sA[1][0]);
    bSm[0] = (unsigned)__cvta_generic_to_shared(&sB[0][0]);
    bSm[1] = (unsigned)__cvta_generic_to_shared(&sB[1][0]);

    const int warp = tid >> 5, lane = tid & 31;
    const int wm = (warp & 1) * 64;      // warp m-origin in tile
    const int wn = (warp >> 1) * 32;     // warp n-origin in tile

    int c[4][4][4];
#pragma unroll
    for (int mt = 0; mt < 4; ++mt)
#pragma unroll
        for (int nt = 0; nt < 4; ++nt)
#pragma unroll
            for (int k = 0; k < 4; ++k) c[mt][nt][k] = 0;

    auto LD = [&](int it, int buf) {
        const int8_t* ag = A  + it * 64 + lco;
        const int8_t* bg = Bp + it * 64 + lco;
        unsigned sa = aSm[buf] + (unsigned)(lr * 80 + lco);
        unsigned sb = bSm[buf] + (unsigned)(lr * 80 + lco);
        CP16(sa,            ag + (size_t)lr * KDIM);
        CP16(sa + 64 * 80,  ag + (size_t)(lr + 64) * KDIM);
        CP16(sb,            bg + (size_t)lr * KDIM);
        CP16(sb + 64 * 80,  bg + (size_t)(lr + 64) * KDIM);
    };

    const int NIT = KDIM / 64;
    LD(0, 0);
    asm volatile("cp.async.commit_group;");

    for (int it = 0; it < NIT; ++it) {
        const int buf = it & 1;
        if (it + 1 < NIT) LD(it + 1, buf ^ 1);
        asm volatile("cp.async.commit_group;");
        asm volatile("cp.async.wait_group 1;");
        __syncthreads();

#pragma unroll
        for (int ks = 0; ks < 2; ++ks) {
            int a[4][4], bfr[4][2];
            const int arow = (lane & 7) + ((lane >> 3) & 1) * 8;
            const int akb  = ks * 32 + ((lane >> 4) << 4);
#pragma unroll
            for (int mt = 0; mt < 4; ++mt) {
                unsigned ad = aSm[buf] + (unsigned)((wm + mt * 16 + arow) * 80 + akb);
                asm volatile("ldmatrix.sync.aligned.m8n8.x4.shared.b16 {%0,%1,%2,%3}, [%4];"
                             : "=r"(a[mt][0]), "=r"(a[mt][1]), "=r"(a[mt][2]), "=r"(a[mt][3])
                             : "r"(ad));
            }
            const int brow = (lane & 7);
            const int bkb  = ks * 32 + ((lane >> 3) & 1) * 16;
#pragma unroll
            for (int nt = 0; nt < 4; ++nt) {
                unsigned bd = bSm[buf] + (unsigned)((wn + nt * 8 + brow) * 80 + bkb);
                asm volatile("ldmatrix.sync.aligned.m8n8.x2.shared.b16 {%0,%1}, [%2];"
                             : "=r"(bfr[nt][0]), "=r"(bfr[nt][1]) : "r"(bd));
            }
#pragma unroll
            for (int mt = 0; mt < 4; ++mt)
#pragma unroll
                for (int nt = 0; nt < 4; ++nt) {
                    asm volatile(
                        "mma.sync.aligned.m16n8k32.row.col.s32.s8.s8.s32 "
                        "{%0,%1,%2,%3}, {%4,%5,%6,%7}, {%8,%9}, {%0,%1,%2,%3};"
                        : "+r"(c[mt][nt][0]), "+r"(c[mt][nt][1]),
                          "+r"(c[mt][nt][2]), "+r"(c[mt][nt][3])
                        : "r"(a[mt][0]), "r"(a[mt][1]), "r"(a[mt][2]), "r"(a[mt][3]),
                          "r"(bfr[nt][0]), "r"(bfr[nt][1]));
                }
        }
        __syncthreads();
    }

    // epilogue
    const int gr = lane >> 2, gc = (lane & 3) * 2;
#pragma unroll
    for (int mt = 0; mt < 4; ++mt) {
#pragma unroll
        for (int nt = 0; nt < 4; ++nt) {
            const int row = bm * 128 + wm + mt * 16 + gr;
            const int col = bn * 128 + wn + nt * 8 + gc;
            if (OUTF) {
                *reinterpret_cast<float2*>(outF + (size_t)row * 4096 + col) =
                    make_float2((float)c[mt][nt][0], (float)c[mt][nt][1]);   // exact: |c|<=4096
                *reinterpret_cast<float2*>(outF + (size_t)(row + 8) * 4096 + col) =
                    make_float2((float)c[mt][nt][2], (float)c[mt][nt][3]);
            } else {
                int* Cz = g_C + (size_t)z * CPLANE;
                *reinterpret_cast<int2*>(Cz + (size_t)row * 4096 + col) =
                    make_int2(c[mt][nt][0], c[mt][nt][1]);
                *reinterpret_cast<int2*>(Cz + (size_t)(row + 8) * 4096 + col) =
                    make_int2(c[mt][nt][2], c[mt][nt][3]);
            }
        }
    }
}

// ---------------- launch ----------------
extern "C" void kernel_launch(void* const* d_in, const int* in_sizes, int n_in,
                              void* d_out, int out_size) {
    const float* x      = (const float*)d_in[0];
    const float* hidden = (const float*)d_in[1];
    const float* Wi     = (const float*)d_in[2];
    const float* Wh     = (const float*)d_in[3];
    const float* Wo     = (const float*)d_in[4];
    float* out = (float*)d_out;
    // tuple = (output, hidden_new), flattened concat
    float* outHid = (out_size >= 67108864) ? (out + (size_t)33554432) : nullptr;

    k_quant  <<< (3u * 4194304u) / 256u, 256 >>> (Wi, Wh, Wo);
    k_limb   <<< (2u * 8388608u) / 256u, 256 >>> (x, hidden);
    k_gemm<8192, false> <<< dim3(32, 64, 3), 256 >>> (nullptr);   // 3 limb planes -> g_C
    k_combine<<< 8388608u / 256u, 256 >>> (outHid);               // pre -> hidden_new
    k_gemm<4096, true>  <<< dim3(32, 64, 1), 256 >>> (out);       // output (exact int)
}